// round 9
// baseline (speedup 1.0000x reference)
#include <cuda_runtime.h>
#include <cstddef>

// Problem constants (B=16, N=M=1024, D=32)
#define CELEM (16 * 1024 * 1024)
#define ROWS  (16 * 1024)
#define NBLK  128                  // persistent blocks (co-resident, <= SM count)

// eps = 1e-3
#define K2F       1442.6951f       // log2(e)/eps
#define EPSLN2F   6.9314718e-4f    // eps*ln2
#define EPSLOGMU  (-6.9314616e-3f) // eps*log(1/1024 + 1e-8)
#define BUCKW     4.0f             // bucket width for C ordering
#define STOP_EPS  0.05f            // stop slack: covers 0.0277 contributor window + fp32 rounding

// Device scratch (allocation-free rule)
__device__ float  g_C  [CELEM];    // raw C  (staging for ordering)
__device__ float  g_CT [CELEM];    // raw C^T
__device__ float  g_CroU[CELEM];   // C values, bucket-ascending per row (u-scan)
__device__ float  g_CroV[CELEM];   // same for C^T rows (v-scan)
__device__ unsigned short g_IdxU[CELEM];   // column index per ordered slot
__device__ unsigned short g_IdxV[CELEM];
__device__ float  g_minCU[ROWS], g_minCV[ROWS];
__device__ float  g_u[ROWS], g_v[ROWS];
__device__ float  g_bp[NBLK];
__device__ int    g_bar_count;
__device__ volatile int g_bar_gen;

// ---------------------------------------------------------------------------
__device__ __forceinline__ void gbarrier() {
    __syncthreads();
    if (threadIdx.x == 0) {
        __threadfence();
        int gen = g_bar_gen;
        if (atomicAdd(&g_bar_count, 1) == NBLK - 1) {
            g_bar_count = 0;
            __threadfence();
            g_bar_gen = gen + 1;
        } else {
            while (g_bar_gen == gen) __nanosleep(64);
        }
        __threadfence();
    }
    __syncthreads();
}

__device__ __forceinline__ float wred_max(float v) {
#pragma unroll
    for (int o = 16; o; o >>= 1) v = fmaxf(v, __shfl_xor_sync(0xffffffffu, v, o));
    return v;
}
__device__ __forceinline__ float wred_sum(float v) {
#pragma unroll
    for (int o = 16; o; o >>= 1) v += __shfl_xor_sync(0xffffffffu, v, o);
    return v;
}

// ---------------------------------------------------------------------------
// Cost matrix (verified R5): raw fp32 C + C^T.
// ---------------------------------------------------------------------------
__global__ void __launch_bounds__(256) k_cost(const float* __restrict__ X,
                                              const float* __restrict__ Y) {
    __shared__ float xs[32][33], ys[32][33], cs[32][33];
    int t  = blockIdx.x;
    int b  = t >> 10;
    int it = (t >> 5) & 31;
    int jt = t & 31;
    int tid = threadIdx.x;
    int r = tid >> 5, d = tid & 31;

#pragma unroll
    for (int k = 0; k < 4; k++) {
        int rr = r + (k << 3);
        xs[rr][d] = X[((size_t)b * 1024 + it * 32 + rr) * 32 + d];
        ys[rr][d] = Y[((size_t)b * 1024 + jt * 32 + rr) * 32 + d];
    }
    __syncthreads();

    int tx = tid & 31, ty = tid >> 5;
#pragma unroll
    for (int k = 0; k < 4; k++) {
        int i = ty * 4 + k;
        float acc = 0.f;
#pragma unroll
        for (int dd = 0; dd < 32; dd++) {
            float diff = xs[i][dd] - ys[tx][dd];
            acc = fmaf(diff, diff, acc);
        }
        cs[i][tx] = acc;
    }
    __syncthreads();

    size_t cbase = (size_t)b << 20;
#pragma unroll
    for (int k = 0; k < 4; k++) {
        int i = ty * 4 + k;
        g_C [cbase + (size_t)(it * 32 + i) * 1024 + jt * 32 + tx] = cs[i][tx];
        g_CT[cbase + (size_t)(jt * 32 + i) * 1024 + it * 32 + tx] = cs[tx][i];
    }
}

// ---------------------------------------------------------------------------
// One-time bucket ordering: per row, stable partition of columns by
// bucket = min(63, floor((C - minC)/4)). Deterministic (integer smem
// atomics + match_any stable ranks, serial batch order within a warp).
// One warp per row. orient: 0 = C->U structures, 1 = C^T->V.
// ---------------------------------------------------------------------------
__global__ void __launch_bounds__(256) k_order(int orient) {
    __shared__ int hist[8][64];
    const float*    Craw = orient ? g_CT   : g_C;
    float*          Cro  = orient ? g_CroV : g_CroU;
    unsigned short* Idx  = orient ? g_IdxV : g_IdxU;
    float*          MnC  = orient ? g_minCV : g_minCU;

    int wid = threadIdx.x >> 5, lane = threadIdx.x & 31;
    int row = blockIdx.x * 8 + wid;
    const float* cr = Craw + ((size_t)row << 10);
    size_t ro = (size_t)row << 10;

    // pass 1: row min
    float mn = 3.4e38f;
#pragma unroll
    for (int k = 0; k < 32; k++) mn = fminf(mn, cr[k * 32 + lane]);
#pragma unroll
    for (int o = 16; o; o >>= 1) mn = fminf(mn, __shfl_xor_sync(0xffffffffu, mn, o));

    // pass 2: histogram (integer adds: deterministic)
    hist[wid][lane] = 0; hist[wid][lane + 32] = 0;
    __syncwarp();
    for (int k = 0; k < 32; k++) {
        float c = cr[k * 32 + lane];
        int bkt = min(63, (int)((c - mn) * 0.25f));
        atomicAdd(&hist[wid][bkt], 1);
    }
    __syncwarp();
    if (lane == 0) {                 // exclusive prefix, serial (deterministic)
        int acc = 0;
#pragma unroll
        for (int bkt = 0; bkt < 64; bkt++) { int t = hist[wid][bkt]; hist[wid][bkt] = acc; acc += t; }
    }
    __syncwarp();

    // pass 3: stable scatter, batches of 32 in column order
    for (int base = 0; base < 1024; base += 32) {
        int j = base + lane;
        float c = cr[j];
        int bkt = min(63, (int)((c - mn) * 0.25f));
        unsigned peers = __match_any_sync(0xffffffffu, bkt);
        int rank   = __popc(peers & ((1u << lane) - 1));
        int leader = __ffs(peers) - 1;
        int boff = 0;
        if (lane == leader) boff = atomicAdd(&hist[wid][bkt], __popc(peers));
        boff = __shfl_sync(0xffffffffu, boff, leader);
        Cro[ro + boff + rank] = c;
        Idx[ro + boff + rank] = (unsigned short)j;
        __syncwarp();
    }
    if (lane == 0) MnC[row] = mn;
}

// ---------------------------------------------------------------------------
// One half-step via ordered prefix scan with sound early stop.
// ---------------------------------------------------------------------------
__device__ __forceinline__ void scan_ord(
    int bid, int tid, int lane, int wid,
    const float* __restrict__ Cro, const unsigned short* __restrict__ Idx,
    const float* __restrict__ minC,
    const float* __restrict__ wsrc, float* __restrict__ zdst,
    float* ws, float* du_s, float* s_tmp)
{
    int b = bid >> 3;
    float wv = wsrc[(b << 10) + tid];
    ws[tid] = wv;
    float bm = wred_max(wv);                    // block max of w (batch-wide)
    if (lane == 0) s_tmp[wid] = bm;
    __syncthreads();
    if (tid < 32) {
        float t = wred_max(s_tmp[lane]);
        if (lane == 0) s_tmp[32] = t;
    }
    __syncthreads();
    float maxw = s_tmp[32];

#pragma unroll 1
    for (int r = 0; r < 4; r++) {
        int rl  = (wid << 2) + r;
        int row = (bid << 7) + rl;
        size_t ro = (size_t)row << 10;
        const float4*  c4 = (const float4*)(Cro + ro);
        const ushort4* i4 = (const ushort4*)(Idx + ro);
        float mnC = minC[row];

        // pass 1: running exact max with early stop
        float m = -3.4e38f;
        int nch = 8;
#pragma unroll 1
        for (int k = 0; k < 8; k++) {
            float4  c  = c4[(k << 5) + lane];
            ushort4 ix = i4[(k << 5) + lane];
            float v0 = ws[ix.x] - c.x;
            float v1 = ws[ix.y] - c.y;
            float v2 = ws[ix.z] - c.z;
            float v3 = ws[ix.w] - c.w;
            m = fmaxf(m, fmaxf(fmaxf(v0, v1), fmaxf(v2, v3)));
            m = wred_max(m);                                   // warp-uniform
            if (k == 7) break;
            float cn = Cro[ro + ((size_t)(k + 1) << 7)];        // broadcast load
            float lo = mnC + (float)min(63, (int)((cn - mnC) * 0.25f)) * BUCKW;
            if (lo > maxw - m + STOP_EPS) { nch = k + 1; break; } // remaining < m - 0.05
        }

        // pass 2: exp-sum over scanned prefix (L1-hot reload)
        float s = 0.f;
#pragma unroll 1
        for (int k = 0; k < nch; k++) {
            float4  c  = c4[(k << 5) + lane];
            ushort4 ix = i4[(k << 5) + lane];
            float v0 = ws[ix.x] - c.x;
            float v1 = ws[ix.y] - c.y;
            float v2 = ws[ix.z] - c.z;
            float v3 = ws[ix.w] - c.w;
            s += exp2f((v0 - m) * K2F) + exp2f((v1 - m) * K2F)
               + exp2f((v2 - m) * K2F) + exp2f((v3 - m) * K2F);
        }
        s = wred_sum(s);

        if (lane == 0) {
            float z = EPSLOGMU - m - EPSLN2F * log2f(s);
            du_s[rl] = fabsf(z - zdst[row]);
            zdst[row] = z;
        }
    }
    __syncthreads();
}

// ---------------------------------------------------------------------------
// Persistent Sinkhorn kernel.
// ---------------------------------------------------------------------------
__global__ void __launch_bounds__(1024, 1) k_sink(float* __restrict__ out) {
    __shared__ float ws[1024];
    __shared__ float du_s[128];
    __shared__ float s_tmp[33];
    __shared__ float s_red[1];
    int tid  = threadIdx.x, bid = blockIdx.x;
    int lane = tid & 31,    wid = tid >> 5;

    if (tid < 128) { int r = (bid << 7) + tid; g_u[r] = 0.f; g_v[r] = 0.f; }
    gbarrier();

    bool will_done = false;
    for (int it = 0; it < 100; it++) {
        // ---- u-update (reads v) ----
        scan_ord(bid, tid, lane, wid, g_CroU, g_IdxU, g_minCU, g_v, g_u, ws, du_s, s_tmp);
        if (wid == 0) {
            float e = du_s[lane] + du_s[lane + 32] + du_s[lane + 64] + du_s[lane + 96];
            e = wred_sum(e);
            if (lane == 0) g_bp[bid] = e;
        }
        gbarrier();

        // all blocks identically: err latch
        if (tid < 32) {
            float a = g_bp[lane] + g_bp[lane + 32] + g_bp[lane + 64] + g_bp[lane + 96];
            a = wred_sum(a);
            if (lane == 0) s_red[0] = a;
        }
        __syncthreads();
        will_done = (s_red[0] * (1.0f / 16.0f) < 0.1f);

        // ---- v-update (triggering iteration's v still applied) ----
        scan_ord(bid, tid, lane, wid, g_CroV, g_IdxV, g_minCV, g_u, g_v, ws, du_s, s_tmp);
        gbarrier();

        if (will_done) break;   // uniform across blocks
    }

    // --------- final: sum_ij exp((u_i + v_j - C_ij)/eps) * C_ij ----------
    {
        int b = bid >> 3;
        float wv = g_v[(b << 10) + tid];
        ws[tid] = wv;
        float bm = wred_max(wv);
        if (lane == 0) s_tmp[wid] = bm;
        __syncthreads();
        if (tid < 32) {
            float t = wred_max(s_tmp[lane]);
            if (lane == 0) s_tmp[32] = t;
        }
        __syncthreads();
        float maxw = s_tmp[32];

#pragma unroll 1
        for (int r = 0; r < 4; r++) {
            int rl  = (wid << 2) + r;
            int row = (bid << 7) + rl;
            size_t ro = (size_t)row << 10;
            const float4*  c4 = (const float4*)(g_CroU + ro);
            const ushort4* i4 = (const ushort4*)(g_IdxU + ro);
            float mnC = g_minCU[row];
            float uk  = g_u[row];

            float s = 0.f;
#pragma unroll 1
            for (int k = 0; k < 8; k++) {
                float4  c  = c4[(k << 5) + lane];
                ushort4 ix = i4[(k << 5) + lane];
                float v0 = ws[ix.x] - c.x;
                float v1 = ws[ix.y] - c.y;
                float v2 = ws[ix.z] - c.z;
                float v3 = ws[ix.w] - c.w;
                s += exp2f((v0 + uk) * K2F) * c.x + exp2f((v1 + uk) * K2F) * c.y
                   + exp2f((v2 + uk) * K2F) * c.z + exp2f((v3 + uk) * K2F) * c.w;
                if (k == 7) break;
                float cn = g_CroU[ro + ((size_t)(k + 1) << 7)];
                float lo = mnC + (float)min(63, (int)((cn - mnC) * 0.25f)) * BUCKW;
                if (lo > maxw + uk + STOP_EPS) break;   // remaining exponents < -0.05/eps
            }
            s = wred_sum(s);
            if (lane == 0) du_s[rl] = s;
        }
        __syncthreads();
        if (wid == 0) {
            float e = du_s[lane] + du_s[lane + 32] + du_s[lane + 64] + du_s[lane + 96];
            e = wred_sum(e);
            if (lane == 0) g_bp[bid] = e;
        }
    }
    gbarrier();
    if (bid == 0 && wid == 0) {
        float e = g_bp[lane] + g_bp[lane + 32] + g_bp[lane + 64] + g_bp[lane + 96];
        e = wred_sum(e);
        if (lane == 0) out[0] = e * (1.0f / 16.0f);   // mean over B
    }
}

// ---------------------------------------------------------------------------
extern "C" void kernel_launch(void* const* d_in, const int* in_sizes, int n_in,
                              void* d_out, int out_size) {
    (void)in_sizes; (void)n_in; (void)out_size;
    const float* X = (const float*)d_in[0];   // output [16,1024,32]
    const float* Y = (const float*)d_in[1];   // labels [16,1024,32]

    k_cost <<<16384, 256>>>(X, Y);
    k_order<<<2048, 256>>>(0);    // C   -> ordered U structures
    k_order<<<2048, 256>>>(1);    // C^T -> ordered V structures
    k_sink <<<NBLK, 1024>>>((float*)d_out);
}

// round 12
// speedup vs baseline: 1.0841x; 1.0841x over previous
#include <cuda_runtime.h>
#include <cuda_fp16.h>
#include <cstddef>

// Problem constants (B=16, N=M=1024, D=32)
#define CELEM (16 * 1024 * 1024)
#define ROWS  (16 * 1024)
#define NBLK  128                  // persistent blocks, 1/SM (proven co-resident R6-R9)

// eps = 1e-3
#define K2F       1442.6951f       // log2(e)/eps
#define EPSLN2F   6.9314718e-4f    // eps*ln2
#define EPSLOGMU  (-6.9314616e-3f) // eps*log(1/1024 + 1e-8)
#define MARGIN    0.6f             // fp16 prefilter margin (proven R5/R6)

// Device scratch (allocation-free rule)
__device__ float  g_C  [CELEM];    // fp32 C
__device__ float  g_CT [CELEM];    // fp32 C^T
__device__ __half g_Ch [CELEM];    // fp16 C  (prefilter)
__device__ __half g_CTh[CELEM];    // fp16 C^T
__device__ float  g_u[ROWS], g_v[ROWS];
__device__ float  g_bp[NBLK];
__device__ int    g_bar_count;
__device__ volatile int g_bar_gen;

// ---------------------------------------------------------------------------
__device__ __forceinline__ void gbarrier() {
    __syncthreads();
    if (threadIdx.x == 0) {
        __threadfence();
        int gen = g_bar_gen;
        if (atomicAdd(&g_bar_count, 1) == NBLK - 1) {
            g_bar_count = 0;
            __threadfence();
            g_bar_gen = gen + 1;
        } else {
            while (g_bar_gen == gen) __nanosleep(64);
        }
        __threadfence();
    }
    __syncthreads();
}

__device__ __forceinline__ float wred_max(float v) {
#pragma unroll
    for (int o = 16; o; o >>= 1) v = fmaxf(v, __shfl_xor_sync(0xffffffffu, v, o));
    return v;
}
__device__ __forceinline__ float wred_sum(float v) {
#pragma unroll
    for (int o = 16; o; o >>= 1) v += __shfl_xor_sync(0xffffffffu, v, o);
    return v;
}

// fp16 prefilter of one 256-elem group slice (8 halves/lane): packed max(w - C)
#define PREF_GRP_H(Q, ACC) do {                                                 \
    uint4 cq = cp[((Q) << 5) + lane];                                           \
    uint4 wq = wp[((Q) << 5) + lane];                                           \
    half2 d0 = __hsub2(*reinterpret_cast<const half2*>(&wq.x),                  \
                       *reinterpret_cast<const half2*>(&cq.x));                 \
    half2 d1 = __hsub2(*reinterpret_cast<const half2*>(&wq.y),                  \
                       *reinterpret_cast<const half2*>(&cq.y));                 \
    half2 d2 = __hsub2(*reinterpret_cast<const half2*>(&wq.z),                  \
                       *reinterpret_cast<const half2*>(&cq.z));                 \
    half2 d3 = __hsub2(*reinterpret_cast<const half2*>(&wq.w),                  \
                       *reinterpret_cast<const half2*>(&cq.w));                 \
    ACC = __hmax2(__hmax2(d0, d1), __hmax2(d2, d3));                            \
} while (0)

// ---------------------------------------------------------------------------
// Cost matrix (verified R5): fp32 + fp16, plus transposes.
// ---------------------------------------------------------------------------
__global__ void __launch_bounds__(256) k_cost(const float* __restrict__ X,
                                              const float* __restrict__ Y) {
    __shared__ float xs[32][33], ys[32][33], cs[32][33];
    int t  = blockIdx.x;
    int b  = t >> 10;
    int it = (t >> 5) & 31;
    int jt = t & 31;
    int tid = threadIdx.x;
    int r = tid >> 5, d = tid & 31;

#pragma unroll
    for (int k = 0; k < 4; k++) {
        int rr = r + (k << 3);
        xs[rr][d] = X[((size_t)b * 1024 + it * 32 + rr) * 32 + d];
        ys[rr][d] = Y[((size_t)b * 1024 + jt * 32 + rr) * 32 + d];
    }
    __syncthreads();

    int tx = tid & 31, ty = tid >> 5;
#pragma unroll
    for (int k = 0; k < 4; k++) {
        int i = ty * 4 + k;
        float acc = 0.f;
#pragma unroll
        for (int dd = 0; dd < 32; dd++) {
            float diff = xs[i][dd] - ys[tx][dd];
            acc = fmaf(diff, diff, acc);
        }
        cs[i][tx] = acc;
    }
    __syncthreads();

    size_t cbase = (size_t)b << 20;
#pragma unroll
    for (int k = 0; k < 4; k++) {
        int i = ty * 4 + k;
        size_t idx  = cbase + (size_t)(it * 32 + i) * 1024 + jt * 32 + tx;
        size_t idxT = cbase + (size_t)(jt * 32 + i) * 1024 + it * 32 + tx;
        float  cv  = cs[i][tx];
        float  cvT = cs[tx][i];
        g_C  [idx]  = cv;
        g_CT [idxT] = cvT;
        g_Ch [idx]  = __float2half_rn(cv);
        g_CTh[idxT] = __float2half_rn(cvT);
    }
}

// ---------------------------------------------------------------------------
// One half-step for this block's 128 rows (4 rows per warp).
// Packed fp16 prefilter (smem fp16 w) -> exact fp32 max + exp-sum (flagged).
// ---------------------------------------------------------------------------
__device__ __forceinline__ void scan_phase(
    int bid, int tid, int lane, int wid,
    const __half* __restrict__ Ch, const float* __restrict__ Cf,
    const float* __restrict__ wsrc, float* __restrict__ zdst,
    float* ws, __half* ws_h, float* du_s)
{
    int b = bid >> 3;                        // 8 blocks per batch
    float wv = wsrc[(b << 10) + tid];
    ws[tid]   = wv;
    ws_h[tid] = __float2half_rn(wv);
    __syncthreads();

    const float4* ws4 = (const float4*)ws;
    const uint4*  wp  = (const uint4*)ws_h;

#pragma unroll 1
    for (int r = 0; r < 4; r++) {
        int rl  = (wid << 2) + r;
        int row = (bid << 7) + rl;
        const uint4*  cp  = (const uint4*) (Ch + ((size_t)row << 10));
        const float4* cf4 = (const float4*)(Cf + ((size_t)row << 10));

        half2 a0, a1, a2, a3;
        PREF_GRP_H(0, a0); PREF_GRP_H(1, a1); PREF_GRP_H(2, a2); PREF_GRP_H(3, a3);

        // packed row max + packed warp reduce; single fp32 conversion at the end
        half2 mm = __hmax2(__hmax2(a0, a1), __hmax2(a2, a3));
#pragma unroll
        for (int o = 16; o; o >>= 1) {
            unsigned u = __shfl_xor_sync(0xffffffffu,
                                         *reinterpret_cast<unsigned*>(&mm), o);
            mm = __hmax2(mm, *reinterpret_cast<half2*>(&u));
        }
        float m = fmaxf(__low2float(mm), __high2float(mm));

        __half thr_h = __float2half_rn(m - MARGIN);
        int msk = (__hgt(__hmax(__low2half(a0), __high2half(a0)), thr_h) ? 1 : 0)
                | (__hgt(__hmax(__low2half(a1), __high2half(a1)), thr_h) ? 2 : 0)
                | (__hgt(__hmax(__low2half(a2), __high2half(a2)), thr_h) ? 4 : 0)
                | (__hgt(__hmax(__low2half(a3), __high2half(a3)), thr_h) ? 8 : 0);

        // exact fp32 max over flagged groups (argmax group guaranteed flagged)
        float me = -3.4e38f;
#pragma unroll 1
        for (int q = 0; q < 4; q++) if ((msk >> q) & 1) {
            int ix = (q << 6) + (lane << 1);
            float4 a  = cf4[ix],  bb = cf4[ix + 1];
            float4 wa = ws4[ix],  wb = ws4[ix + 1];
            me = fmaxf(me, fmaxf(fmaxf(wa.x - a.x,  wa.y - a.y),
                                 fmaxf(wa.z - a.z,  wa.w - a.w)));
            me = fmaxf(me, fmaxf(fmaxf(wb.x - bb.x, wb.y - bb.y),
                                 fmaxf(wb.z - bb.z, wb.w - bb.w)));
        }
        me = wred_max(me);

        float s = 0.f;
#pragma unroll 1
        for (int q = 0; q < 4; q++) if ((msk >> q) & 1) {
            int ix = (q << 6) + (lane << 1);
            float4 a  = cf4[ix],  bb = cf4[ix + 1];   // L1 hit
            float4 wa = ws4[ix],  wb = ws4[ix + 1];
            s += exp2f((wa.x - a.x  - me) * K2F) + exp2f((wa.y - a.y  - me) * K2F)
               + exp2f((wa.z - a.z  - me) * K2F) + exp2f((wa.w - a.w  - me) * K2F)
               + exp2f((wb.x - bb.x - me) * K2F) + exp2f((wb.y - bb.y - me) * K2F)
               + exp2f((wb.z - bb.z - me) * K2F) + exp2f((wb.w - bb.w - me) * K2F);
        }
        s = wred_sum(s);

        if (lane == 0) {
            float z = EPSLOGMU - me - EPSLN2F * log2f(s);
            du_s[rl] = fabsf(z - zdst[row]);
            zdst[row] = z;
        }
    }
    __syncthreads();
}

// ---------------------------------------------------------------------------
// Persistent Sinkhorn kernel: 128 blocks (1/SM), 128 rows per block.
// ---------------------------------------------------------------------------
__global__ void __launch_bounds__(1024, 1) k_sink(float* __restrict__ out) {
    __shared__ float  ws[1024];
    __shared__ __half ws_h[1024];
    __shared__ float  du_s[128];
    __shared__ float  s_red[1];
    int tid  = threadIdx.x, bid = blockIdx.x;
    int lane = tid & 31,    wid = tid >> 5;

    if (tid < 128) { int r = (bid << 7) + tid; g_u[r] = 0.f; g_v[r] = 0.f; }
    gbarrier();

    bool will_done = false;
    for (int it = 0; it < 100; it++) {
        // ---- u-update (reads v) ----
        scan_phase(bid, tid, lane, wid, g_Ch, g_C, g_v, g_u, ws, ws_h, du_s);
        if (wid == 0) {
            float e = du_s[lane] + du_s[lane + 32] + du_s[lane + 64] + du_s[lane + 96];
            e = wred_sum(e);
            if (lane == 0) g_bp[bid] = e;
        }
        gbarrier();

        // all blocks identically: err latch (uniform decision, no flag polling)
        if (tid < 32) {
            float a = g_bp[lane] + g_bp[lane + 32] + g_bp[lane + 64] + g_bp[lane + 96];
            a = wred_sum(a);
            if (lane == 0) s_red[0] = a;
        }
        __syncthreads();
        will_done = (s_red[0] * (1.0f / 16.0f) < 0.1f);

        // ---- v-update (triggering iteration's v still applied) ----
        scan_phase(bid, tid, lane, wid, g_CTh, g_CT, g_u, g_v, ws, ws_h, du_s);
        gbarrier();

        if (will_done) break;   // uniform across blocks
    }

    // --------- final: sum_ij exp((u_i + v_j - C_ij)/eps) * C_ij ----------
    {
        int b = bid >> 3;
        float wv = g_v[(b << 10) + tid];
        ws[tid]   = wv;
        ws_h[tid] = __float2half_rn(wv);
        __syncthreads();
        const float4* ws4 = (const float4*)ws;
        const uint4*  wp  = (const uint4*)ws_h;

#pragma unroll 1
        for (int r = 0; r < 4; r++) {
            int rl  = (wid << 2) + r;
            int row = (bid << 7) + rl;
            const uint4*  cp  = (const uint4*) (g_Ch + ((size_t)row << 10));
            const float4* cf4 = (const float4*)(g_C  + ((size_t)row << 10));
            float uk = g_u[row];

            half2 a0, a1, a2, a3;
            PREF_GRP_H(0, a0); PREF_GRP_H(1, a1); PREF_GRP_H(2, a2); PREF_GRP_H(3, a3);

            // contribute iff (val + uk)/eps exponent > -~72 bits (fp16 slack folded)
            __half cut = __float2half_rn(-0.65f - uk);
            int msk = (__hgt(__hmax(__low2half(a0), __high2half(a0)), cut) ? 1 : 0)
                    | (__hgt(__hmax(__low2half(a1), __high2half(a1)), cut) ? 2 : 0)
                    | (__hgt(__hmax(__low2half(a2), __high2half(a2)), cut) ? 4 : 0)
                    | (__hgt(__hmax(__low2half(a3), __high2half(a3)), cut) ? 8 : 0);

            float s = 0.f;
#pragma unroll 1
            for (int q = 0; q < 4; q++) if ((msk >> q) & 1) {
                int ix = (q << 6) + (lane << 1);
                float4 a  = cf4[ix],  bb = cf4[ix + 1];
                float4 wa = ws4[ix],  wb = ws4[ix + 1];
                s += exp2f((wa.x - a.x  + uk) * K2F) * a.x
                   + exp2f((wa.y - a.y  + uk) * K2F) * a.y
                   + exp2f((wa.z - a.z  + uk) * K2F) * a.z
                   + exp2f((wa.w - a.w  + uk) * K2F) * a.w
                   + exp2f((wb.x - bb.x + uk) * K2F) * bb.x
                   + exp2f((wb.y - bb.y + uk) * K2F) * bb.y
                   + exp2f((wb.z - bb.z + uk) * K2F) * bb.z
                   + exp2f((wb.w - bb.w + uk) * K2F) * bb.w;
            }
            s = wred_sum(s);
            if (lane == 0) du_s[rl] = s;
        }
        __syncthreads();
        if (wid == 0) {
            float e = du_s[lane] + du_s[lane + 32] + du_s[lane + 64] + du_s[lane + 96];
            e = wred_sum(e);
            if (lane == 0) g_bp[bid] = e;
        }
    }
    gbarrier();
    if (bid == 0 && wid == 0) {
        float e = g_bp[lane] + g_bp[lane + 32] + g_bp[lane + 64] + g_bp[lane + 96];
        e = wred_sum(e);
        if (lane == 0) out[0] = e * (1.0f / 16.0f);   // mean over B
    }
}

// ---------------------------------------------------------------------------
extern "C" void kernel_launch(void* const* d_in, const int* in_sizes, int n_in,
                              void* d_out, int out_size) {
    (void)in_sizes; (void)n_in; (void)out_size;
    const float* X = (const float*)d_in[0];   // output [16,1024,32]
    const float* Y = (const float*)d_in[1];   // labels [16,1024,32]

    k_cost<<<16384, 256>>>(X, Y);
    k_sink<<<NBLK, 1024>>>((float*)d_out);
}

// round 13
// speedup vs baseline: 1.5770x; 1.4547x over previous
#include <cuda_runtime.h>
#include <cuda_fp16.h>
#include <cstddef>

// Problem constants (B=16, N=M=1024, D=32)
#define CELEM (16 * 1024 * 1024)
#define ROWS  (16 * 1024)
#define NBLK  128                  // persistent blocks (co-resident, proven R6)

// eps = 1e-3
#define K2F       1442.6951f       // log2(e)/eps
#define EPSLN2F   6.9314718e-4f    // eps*ln2
#define EPSLOGMU  (-6.9314616e-3f) // eps*log(1/1024 + 1e-8)
#define MARGIN    0.6f             // fp16 prefilter margin (proven R5/R6)

// Device scratch (allocation-free rule)
__device__ float  g_C  [CELEM];    // fp32 C  (exact pass + final)
__device__ float  g_CT [CELEM];    // fp32 C^T
__device__ __half g_Ch [CELEM];    // fp16 C  (prefilter)
__device__ __half g_CTh[CELEM];    // fp16 C^T
__device__ float  g_u[ROWS], g_v[ROWS];
__device__ float  g_bp[NBLK];
__device__ int    g_done;
__device__ int    g_bar_count;
__device__ volatile int g_bar_gen;

// ---------------------------------------------------------------------------
__device__ __forceinline__ void gbarrier() {
    __syncthreads();
    if (threadIdx.x == 0) {
        __threadfence();
        int gen = g_bar_gen;
        if (atomicAdd(&g_bar_count, 1) == NBLK - 1) {
            g_bar_count = 0;
            __threadfence();
            g_bar_gen = gen + 1;
        } else {
            while (g_bar_gen == gen) __nanosleep(64);
        }
        __threadfence();
    }
    __syncthreads();
}

__device__ __forceinline__ float wred_max(float v) {
#pragma unroll
    for (int o = 16; o; o >>= 1) v = fmaxf(v, __shfl_xor_sync(0xffffffffu, v, o));
    return v;
}
__device__ __forceinline__ float wred_sum(float v) {
#pragma unroll
    for (int o = 16; o; o >>= 1) v += __shfl_xor_sync(0xffffffffu, v, o);
    return v;
}

// fp16 prefilter of group Q (8 halves/lane = 256 elems): TWO subgroup maxima.
// Subgroup A = first 4 halves of each lane's uint4, B = last 4.
#define PREF_GRP2(Q, DA, DB) do {                                               \
    uint4 cq = cp[((Q) << 5) + lane];                                           \
    half2 d0 = __hsub2(w2[(Q)*4+0], *reinterpret_cast<const half2*>(&cq.x));    \
    half2 d1 = __hsub2(w2[(Q)*4+1], *reinterpret_cast<const half2*>(&cq.y));    \
    half2 d2 = __hsub2(w2[(Q)*4+2], *reinterpret_cast<const half2*>(&cq.z));    \
    half2 d3 = __hsub2(w2[(Q)*4+3], *reinterpret_cast<const half2*>(&cq.w));    \
    half2 mA = __hmax2(d0, d1);                                                 \
    half2 mB = __hmax2(d2, d3);                                                 \
    DA = fmaxf(__low2float(mA), __high2float(mA));                              \
    DB = fmaxf(__low2float(mB), __high2float(mB));                              \
} while (0)

#define BUILD_W2() do {                                                         \
    _Pragma("unroll")                                                           \
    for (int q = 0; q < 4; q++) {                                               \
        float4 wa = ws4[(q << 6) + (lane << 1)];                                \
        float4 wb = ws4[(q << 6) + (lane << 1) + 1];                            \
        w2[q*4+0] = __floats2half2_rn(wa.x, wa.y);                              \
        w2[q*4+1] = __floats2half2_rn(wa.z, wa.w);                              \
        w2[q*4+2] = __floats2half2_rn(wb.x, wb.y);                              \
        w2[q*4+3] = __floats2half2_rn(wb.z, wb.w);                              \
    }                                                                           \
} while (0)

// ---------------------------------------------------------------------------
// Cost matrix (verified R5): fp32 + fp16, plus transposes.
// ---------------------------------------------------------------------------
__global__ void __launch_bounds__(256) k_cost(const float* __restrict__ X,
                                              const float* __restrict__ Y) {
    __shared__ float xs[32][33], ys[32][33], cs[32][33];
    int t  = blockIdx.x;
    int b  = t >> 10;
    int it = (t >> 5) & 31;
    int jt = t & 31;
    int tid = threadIdx.x;
    int r = tid >> 5, d = tid & 31;

#pragma unroll
    for (int k = 0; k < 4; k++) {
        int rr = r + (k << 3);
        xs[rr][d] = X[((size_t)b * 1024 + it * 32 + rr) * 32 + d];
        ys[rr][d] = Y[((size_t)b * 1024 + jt * 32 + rr) * 32 + d];
    }
    __syncthreads();

    int tx = tid & 31, ty = tid >> 5;
#pragma unroll
    for (int k = 0; k < 4; k++) {
        int i = ty * 4 + k;
        float acc = 0.f;
#pragma unroll
        for (int dd = 0; dd < 32; dd++) {
            float diff = xs[i][dd] - ys[tx][dd];
            acc = fmaf(diff, diff, acc);
        }
        cs[i][tx] = acc;
    }
    __syncthreads();

    size_t cbase = (size_t)b << 20;
#pragma unroll
    for (int k = 0; k < 4; k++) {
        int i = ty * 4 + k;
        size_t idx  = cbase + (size_t)(it * 32 + i) * 1024 + jt * 32 + tx;
        size_t idxT = cbase + (size_t)(jt * 32 + i) * 1024 + it * 32 + tx;
        float  cv  = cs[i][tx];
        float  cvT = cs[tx][i];
        g_C  [idx]  = cv;
        g_CT [idxT] = cvT;
        g_Ch [idx]  = __float2half_rn(cv);
        g_CTh[idxT] = __float2half_rn(cvT);
    }
}

// ---------------------------------------------------------------------------
// One half-step for this block's 128 rows (champion structure, 8-bit masks).
// ---------------------------------------------------------------------------
template <bool MODE0>
__device__ __forceinline__ void scan_phase(
    int bid, int tid, int lane, int wid,
    const __half* __restrict__ Ch, const float* __restrict__ Cf,
    const float* __restrict__ wsrc, float* __restrict__ zdst,
    float* ws, float* du_s)
{
    int b = bid >> 3;                       // batch of this block's 128 rows
    ws[tid] = wsrc[(b << 10) + tid];        // stage dual vector (fp32)
    __syncthreads();

    const float4* ws4 = (const float4*)ws;
    half2 w2[16];
    BUILD_W2();

#pragma unroll 1
    for (int r = 0; r < 4; r++) {
        int rl  = (wid << 2) + r;
        int row = (bid << 7) + rl;
        const uint4*  cp  = (const uint4*) (Ch + ((size_t)row << 10));
        const float4* cf4 = (const float4*)(Cf + ((size_t)row << 10));

        float gm[8];
        PREF_GRP2(0, gm[0], gm[1]);
        PREF_GRP2(1, gm[2], gm[3]);
        PREF_GRP2(2, gm[4], gm[5]);
        PREF_GRP2(3, gm[6], gm[7]);

        float m = gm[0];
#pragma unroll
        for (int g = 1; g < 8; g++) m = fmaxf(m, gm[g]);
        m = wred_max(m);

        float thr = m - MARGIN;
        int msk = 0;
#pragma unroll
        for (int g = 0; g < 8; g++) msk |= (gm[g] > thr) << g;

        // exact fp32 max over flagged subgroups (argmax guaranteed flagged)
        float me = -3.4e38f;
#pragma unroll 1
        for (int q = 0; q < 4; q++) {
            int ix = (q << 6) + (lane << 1);
            if ((msk >> (2 * q)) & 1) {
                float4 a  = cf4[ix];
                float4 wa = ws4[ix];
                me = fmaxf(me, fmaxf(fmaxf(wa.x - a.x, wa.y - a.y),
                                     fmaxf(wa.z - a.z, wa.w - a.w)));
            }
            if ((msk >> (2 * q + 1)) & 1) {
                float4 bb = cf4[ix + 1];
                float4 wb = ws4[ix + 1];
                me = fmaxf(me, fmaxf(fmaxf(wb.x - bb.x, wb.y - bb.y),
                                     fmaxf(wb.z - bb.z, wb.w - bb.w)));
            }
        }
        me = wred_max(me);

        float s = 0.f;
#pragma unroll 1
        for (int q = 0; q < 4; q++) {
            int ix = (q << 6) + (lane << 1);
            if ((msk >> (2 * q)) & 1) {
                float4 a  = cf4[ix];                  // L1 hit
                float4 wa = ws4[ix];
                s += exp2f((wa.x - a.x - me) * K2F) + exp2f((wa.y - a.y - me) * K2F)
                   + exp2f((wa.z - a.z - me) * K2F) + exp2f((wa.w - a.w - me) * K2F);
            }
            if ((msk >> (2 * q + 1)) & 1) {
                float4 bb = cf4[ix + 1];
                float4 wb = ws4[ix + 1];
                s += exp2f((wb.x - bb.x - me) * K2F) + exp2f((wb.y - bb.y - me) * K2F)
                   + exp2f((wb.z - bb.z - me) * K2F) + exp2f((wb.w - bb.w - me) * K2F);
            }
        }
        s = wred_sum(s);

        if (lane == 0) {
            float z = EPSLOGMU - me - EPSLN2F * log2f(s);
            if (MODE0) du_s[rl] = fabsf(z - zdst[row]);
            zdst[row] = z;
        }
    }

    if (MODE0) {
        __syncthreads();
        if (wid == 0) {
            float e = du_s[lane] + du_s[lane + 32] + du_s[lane + 64] + du_s[lane + 96];
            e = wred_sum(e);
            if (lane == 0) g_bp[bid] = e;
        }
    }
}

// ---------------------------------------------------------------------------
// Persistent Sinkhorn kernel (champion control flow).
// ---------------------------------------------------------------------------
__global__ void __launch_bounds__(1024, 1) k_sink(float* __restrict__ out) {
    __shared__ float ws[1024];
    __shared__ float du_s[128];
    int tid  = threadIdx.x, bid = blockIdx.x;
    int lane = tid & 31,    wid = tid >> 5;

    // re-init per graph replay
    if (tid < 128) { int r = (bid << 7) + tid; g_u[r] = 0.f; g_v[r] = 0.f; }
    if (bid == 0 && tid == 0) g_done = 0;
    gbarrier();

    for (int it = 0; it < 100; it++) {
        int done = *(volatile int*)&g_done;     // frozen once latched (ref semantics)
        if (!done)
            scan_phase<true >(bid, tid, lane, wid, g_Ch,  g_C,  g_v, g_u, ws, du_s);
        gbarrier();
        if (!done) {
            if (bid == 0 && wid == 0) {         // err from this iteration's du
                float e = g_bp[lane] + g_bp[lane + 32] + g_bp[lane + 64] + g_bp[lane + 96];
                e = wred_sum(e);
                if (lane == 0 && e * (1.0f / 16.0f) < 0.1f) g_done = 1;
            }
            // triggering iteration's v-update still applied (matches reference)
            scan_phase<false>(bid, tid, lane, wid, g_CTh, g_CT, g_u, g_v, ws, du_s);
        }
        gbarrier();
    }

    // --------- final: sum_ij exp((u_i + v_j - C_ij)/eps) * C_ij ----------
    {
        int b = bid >> 3;
        ws[tid] = g_v[(b << 10) + tid];
        __syncthreads();
        const float4* ws4 = (const float4*)ws;
        half2 w2[16];
        BUILD_W2();

#pragma unroll 1
        for (int r = 0; r < 4; r++) {
            int rl  = (wid << 2) + r;
            int row = (bid << 7) + rl;
            const uint4*  cp  = (const uint4*) (g_Ch + ((size_t)row << 10));
            const float4* cf4 = (const float4*)(g_C  + ((size_t)row << 10));
            float uk = g_u[row];

            float gm[8];
            PREF_GRP2(0, gm[0], gm[1]);
            PREF_GRP2(1, gm[2], gm[3]);
            PREF_GRP2(2, gm[4], gm[5]);
            PREF_GRP2(3, gm[6], gm[7]);

            // contribute iff exp2 exponent > -~900 bits incl fp16 slack
            float cut = -0.65f - uk;
            int msk = 0;
#pragma unroll
            for (int g = 0; g < 8; g++) msk |= (gm[g] > cut) << g;

            float s = 0.f;
#pragma unroll 1
            for (int q = 0; q < 4; q++) {
                int ix = (q << 6) + (lane << 1);
                if ((msk >> (2 * q)) & 1) {
                    float4 a  = cf4[ix];
                    float4 wa = ws4[ix];
                    s += exp2f((wa.x - a.x + uk) * K2F) * a.x
                       + exp2f((wa.y - a.y + uk) * K2F) * a.y
                       + exp2f((wa.z - a.z + uk) * K2F) * a.z
                       + exp2f((wa.w - a.w + uk) * K2F) * a.w;
                }
                if ((msk >> (2 * q + 1)) & 1) {
                    float4 bb = cf4[ix + 1];
                    float4 wb = ws4[ix + 1];
                    s += exp2f((wb.x - bb.x + uk) * K2F) * bb.x
                       + exp2f((wb.y - bb.y + uk) * K2F) * bb.y
                       + exp2f((wb.z - bb.z + uk) * K2F) * bb.z
                       + exp2f((wb.w - bb.w + uk) * K2F) * bb.w;
                }
            }
            s = wred_sum(s);
            if (lane == 0) du_s[rl] = s;
        }
        __syncthreads();
        if (wid == 0) {
            float e = du_s[lane] + du_s[lane + 32] + du_s[lane + 64] + du_s[lane + 96];
            e = wred_sum(e);
            if (lane == 0) g_bp[bid] = e;
        }
    }
    gbarrier();
    if (bid == 0 && wid == 0) {
        float e = g_bp[lane] + g_bp[lane + 32] + g_bp[lane + 64] + g_bp[lane + 96];
        e = wred_sum(e);
        if (lane == 0) out[0] = e * (1.0f / 16.0f);   // mean over B
    }
}

// ---------------------------------------------------------------------------
extern "C" void kernel_launch(void* const* d_in, const int* in_sizes, int n_in,
                              void* d_out, int out_size) {
    (void)in_sizes; (void)n_in; (void)out_size;
    const float* X = (const float*)d_in[0];   // output [16,1024,32]
    const float* Y = (const float*)d_in[1];   // labels [16,1024,32]

    k_cost<<<16384, 256>>>(X, Y);
    k_sink<<<NBLK, 1024>>>((float*)d_out);
}